// round 4
// baseline (speedup 1.0000x reference)
#include <cuda_runtime.h>

#define N_JOINTS 50
#define N_EDGES  47
#define CH       151
#define EPS_TINY 1.17549435e-38f

// Skeleton edges (parent, child)
__constant__ int c_par[N_EDGES] = {
    0,1,2,3,1,5,6,8,8,8,8,8,9,10,11,13,14,15,17,18,19,21,22,23,
    25,26,27,29,29,29,29,29,30,31,32,34,35,36,38,39,40,42,43,44,46,47,48};
__constant__ int c_chi[N_EDGES] = {
    1,2,3,29,5,6,8,9,13,17,21,25,10,11,12,14,15,16,18,19,20,22,23,24,
    26,27,28,30,34,38,42,46,31,32,33,35,36,37,39,40,41,43,44,45,47,48,49};

// Global scratch accumulators (no device allocation allowed)
__device__ double g_acc[2];

__global__ void init_acc_kernel() {
    g_acc[0] = 0.0;
    g_acc[1] = 0.0;
}

#define WARPS_PER_BLOCK 8
#define ROWS_PER_GRP    4
#define GRP_FLOATS      (ROWS_PER_GRP * CH)   /* 604 */
#define GRP_VEC4        (GRP_FLOATS / 4)      /* 151 */
#define SMEM_STRIDE     (GRP_FLOATS + 4)      /* 608, pad to dodge conflicts */

__global__ void __launch_bounds__(256, 4)
reg_loss_kernel(const float* __restrict__ preds,
                const float* __restrict__ targets,
                int groups)   // rows / 4
{
    __shared__ float s_pm[WARPS_PER_BLOCK][SMEM_STRIDE];
    __shared__ float s_tm[WARPS_PER_BLOCK][SMEM_STRIDE];
    __shared__ float s_red[2][WARPS_PER_BLOCK];

    const int lane    = threadIdx.x & 31;
    const int wlocal  = threadIdx.x >> 5;
    const int gwarp   = (blockIdx.x * blockDim.x + threadIdx.x) >> 5;
    const int nwarps  = (gridDim.x * blockDim.x) >> 5;

    float* pm = s_pm[wlocal];
    float* tm = s_tm[wlocal];

    float l1_acc  = 0.0f;
    float vel_acc = 0.0f;

    for (int g = gwarp; g < groups; g += nwarps) {
        // group of 4 rows: 604 floats = 151 float4, 16B-aligned since g*604 % 4 == 0
        const float4* __restrict__ p4 =
            (const float4*)(preds   + (size_t)g * GRP_FLOATS);
        const float4* __restrict__ t4 =
            (const float4*)(targets + (size_t)g * GRP_FLOATS);

        // ---- stage 1: vectorized masked load + L1 term ----
        #pragma unroll 5
        for (int i = lane; i < GRP_VEC4; i += 32) {
            float4 tv = t4[i];
            float4 pv = p4[i];

            float m0 = (tv.x != 0.0f) ? 1.0f : 0.0f;
            float m1 = (tv.y != 0.0f) ? 1.0f : 0.0f;
            float m2 = (tv.z != 0.0f) ? 1.0f : 0.0f;
            float m3 = (tv.w != 0.0f) ? 1.0f : 0.0f;

            float pm0 = pv.x * m0, tm0 = tv.x * m0;
            float pm1 = pv.y * m1, tm1 = tv.y * m1;
            float pm2 = pv.z * m2, tm2 = tv.z * m2;
            float pm3 = pv.w * m3, tm3 = tv.w * m3;

            l1_acc += fabsf(pm0 - tm0) + fabsf(pm1 - tm1)
                    + fabsf(pm2 - tm2) + fabsf(pm3 - tm3);

            int j = i * 4;
            pm[j]   = pm0;  tm[j]   = tm0;
            pm[j+1] = pm1;  tm[j+1] = tm1;
            pm[j+2] = pm2;  tm[j+2] = tm2;
            pm[j+3] = pm3;  tm[j+3] = tm3;
        }
        __syncwarp();

        // ---- stage 2: 4 rows x 47 edges = 188 edge tasks ----
        #pragma unroll 6
        for (int tsk = lane; tsk < ROWS_PER_GRP * N_EDGES; tsk += 32) {
            int r    = tsk / N_EDGES;
            int e    = tsk - r * N_EDGES;
            int base = r * CH;

            int a = base + c_par[e] * 3;
            int b = base + c_chi[e] * 3;

            float dp0 = pm[a]   - pm[b];
            float dp1 = pm[a+1] - pm[b+1];
            float dp2 = pm[a+2] - pm[b+2];
            float dt0 = tm[a]   - tm[b];
            float dt1 = tm[a+1] - tm[b+1];
            float dt2 = tm[a+2] - tm[b+2];

            float lp = sqrtf(dp0*dp0 + dp1*dp1 + dp2*dp2);
            float lt = sqrtf(dt0*dt0 + dt1*dt1 + dt2*dt2);
            float ip = 1.0f / (lp + EPS_TINY);
            float it = 1.0f / (lt + EPS_TINY);

            // direction mask = raw channel mask at c*47+e (post-transpose layout)
            float m0 = (tm[base + e]      != 0.0f) ? 1.0f : 0.0f;
            float m1 = (tm[base + 47 + e] != 0.0f) ? 1.0f : 0.0f;
            float m2 = (tm[base + 94 + e] != 0.0f) ? 1.0f : 0.0f;

            float d0 = dp0 * ip - dt0 * it;
            float d1 = dp1 * ip - dt1 * it;
            float d2 = dp2 * ip - dt2 * it;

            vel_acc += m0 * d0 * d0 + m1 * d1 * d1 + m2 * d2 * d2;
        }
        __syncwarp();  // protect smem before next group overwrites it
    }

    // ---- warp reduce ----
    #pragma unroll
    for (int o = 16; o > 0; o >>= 1) {
        l1_acc  += __shfl_down_sync(0xFFFFFFFFu, l1_acc,  o);
        vel_acc += __shfl_down_sync(0xFFFFFFFFu, vel_acc, o);
    }
    if (lane == 0) {
        s_red[0][wlocal] = l1_acc;
        s_red[1][wlocal] = vel_acc;
    }
    __syncthreads();

    // ---- block reduce + 2 double atomics per block ----
    if (threadIdx.x == 0) {
        float a = 0.0f, v = 0.0f;
        #pragma unroll
        for (int i = 0; i < WARPS_PER_BLOCK; i++) {
            a += s_red[0][i];
            v += s_red[1][i];
        }
        atomicAdd(&g_acc[0], (double)a);
        atomicAdd(&g_acc[1], (double)v);
    }
}

__global__ void finalize_kernel(float* __restrict__ out,
                                double n_l1, double n_vel)
{
    double l1  = g_acc[0] / n_l1;
    double vel = g_acc[1] / n_vel;
    out[0] = (float)(l1 + 0.1 * vel);
}

extern "C" void kernel_launch(void* const* d_in, const int* in_sizes, int n_in,
                              void* d_out, int out_size)
{
    const float* preds   = (const float*)d_in[0];
    const float* targets = (const float*)d_in[1];
    float* out = (float*)d_out;

    int n      = in_sizes[0];
    int rows   = n / CH;              // B*T = 131072
    int groups = rows / ROWS_PER_GRP; // 32768 (rows divisible by 4)

    init_acc_kernel<<<1, 1>>>();

    // 148 SMs * 8 blocks -> 9472 warps, ~3.5 groups (14 rows) per warp
    int blocks = 1184;
    reg_loss_kernel<<<blocks, 256>>>(preds, targets, groups);

    finalize_kernel<<<1, 1>>>(out,
                              (double)rows * (double)CH,
                              (double)rows * (double)(N_EDGES * 3));
}

// round 5
// speedup vs baseline: 1.7140x; 1.7140x over previous
#include <cuda_runtime.h>
#include <cstdint>

#define CH        151
#define N_EDGES   47
#define RPT       32                   // rows per tile == lanes per warp
#define TILE_F    (RPT * CH)           // 4832 floats, contiguous rows
#define TILE_V4   (TILE_F / 4)         // 1208 float4 (tile start is 16B-aligned)
#define NWARP     5
#define THREADS   (NWARP * 32)
#define SMEM_BYTES (NWARP * 2 * TILE_F * 4)   // 193,280 B dynamic

// Skeleton edges (parent, child)
__constant__ int c_par[N_EDGES] = {
    0,1,2,3,1,5,6,8,8,8,8,8,9,10,11,13,14,15,17,18,19,21,22,23,
    25,26,27,29,29,29,29,29,30,31,32,34,35,36,38,39,40,42,43,44,46,47,48};
__constant__ int c_chi[N_EDGES] = {
    1,2,3,29,5,6,8,9,13,17,21,25,10,11,12,14,15,16,18,19,20,22,23,24,
    26,27,28,30,34,38,42,46,31,32,33,35,36,37,39,40,41,43,44,45,47,48,49};

__device__ double g_acc[2];

__global__ void init_acc_kernel() { g_acc[0] = 0.0; g_acc[1] = 0.0; }

__device__ __forceinline__ void cp16(void* s, const void* g) {
    uint32_t sa = (uint32_t)__cvta_generic_to_shared(s);
    asm volatile("cp.async.cg.shared.global [%0], [%1], 16;" :: "r"(sa), "l"(g));
}

// Process one full row (151 channels) given raw p/t pointers.
// tm == t (mask is (t!=0), and t*mask == t); only preds need masking.
__device__ __forceinline__ void process_row(const float* __restrict__ p,
                                            const float* __restrict__ t,
                                            const int* __restrict__ s_a,
                                            const int* __restrict__ s_b,
                                            float& l1_acc, float& vel_acc)
{
    // ---- L1 over all 151 channels: (t!=0) * |p - t| ----
    float l1 = 0.f;
    #pragma unroll 8
    for (int i = 0; i < CH; i++) {
        float tv = t[i];
        float pv = p[i];
        l1 += (tv != 0.f) ? fabsf(pv - tv) : 0.f;
    }
    l1_acc += l1;

    // ---- 47 edge directions ----
    float vel = 0.f;
    #pragma unroll 4
    for (int e = 0; e < N_EDGES; e++) {
        int a = s_a[e];
        int b = s_b[e];

        float ta0 = t[a],   ta1 = t[a+1], ta2 = t[a+2];
        float tb0 = t[b],   tb1 = t[b+1], tb2 = t[b+2];
        float pa0 = p[a],   pa1 = p[a+1], pa2 = p[a+2];
        float pb0 = p[b],   pb1 = p[b+1], pb2 = p[b+2];

        // masked preds (mask from targets)
        float qa0 = (ta0 != 0.f) ? pa0 : 0.f;
        float qa1 = (ta1 != 0.f) ? pa1 : 0.f;
        float qa2 = (ta2 != 0.f) ? pa2 : 0.f;
        float qb0 = (tb0 != 0.f) ? pb0 : 0.f;
        float qb1 = (tb1 != 0.f) ? pb1 : 0.f;
        float qb2 = (tb2 != 0.f) ? pb2 : 0.f;

        float dp0 = qa0 - qb0, dp1 = qa1 - qb1, dp2 = qa2 - qb2;
        float dt0 = ta0 - tb0, dt1 = ta1 - tb1, dt2 = ta2 - tb2;

        float np = fmaf(dp0, dp0, fmaf(dp1, dp1, dp2 * dp2));
        float nt = fmaf(dt0, dt0, fmaf(dt1, dt1, dt2 * dt2));

        // ref: diff/(sqrt(n)+tiny); n==0 -> contribution 0; n>0 -> rsqrt
        float ip = (np > 0.f) ? rsqrtf(np) : 0.f;
        float it = (nt > 0.f) ? rsqrtf(nt) : 0.f;

        float d0 = dp0 * ip - dt0 * it;
        float d1 = dp1 * ip - dt1 * it;
        float d2 = dp2 * ip - dt2 * it;

        // direction mask = raw channel mask at c*47+e (post-transpose layout)
        float m0 = t[e];
        float m1 = t[47 + e];
        float m2 = t[94 + e];

        vel += ((m0 != 0.f) ? d0 * d0 : 0.f)
             + ((m1 != 0.f) ? d1 * d1 : 0.f)
             + ((m2 != 0.f) ? d2 * d2 : 0.f);
    }
    vel_acc += vel;
}

extern __shared__ float smem_dyn[];

__global__ void __launch_bounds__(THREADS, 1)
reg_loss_kernel(const float* __restrict__ preds,
                const float* __restrict__ targets,
                int tiles, int rows)
{
    __shared__ int   s_a[N_EDGES], s_b[N_EDGES];
    __shared__ float s_red[2][NWARP];

    const int lane   = threadIdx.x & 31;
    const int wloc   = threadIdx.x >> 5;
    const int gwarp  = blockIdx.x * NWARP + wloc;
    const int nwarps = gridDim.x * NWARP;

    if (threadIdx.x < N_EDGES) {
        s_a[threadIdx.x] = 3 * c_par[threadIdx.x];
        s_b[threadIdx.x] = 3 * c_chi[threadIdx.x];
    }
    __syncthreads();

    // per-warp private tile buffers; row stride 151 (odd) -> bank-conflict-free
    float* sP = smem_dyn + wloc * (2 * TILE_F);
    float* sT = sP + TILE_F;

    float l1_acc = 0.f, vel_acc = 0.f;

    for (int tile = gwarp; tile < tiles; tile += nwarps) {
        const float4* gp = (const float4*)(preds   + (size_t)tile * TILE_F);
        const float4* gt = (const float4*)(targets + (size_t)tile * TILE_F);
        float4* dP = (float4*)sP;
        float4* dT = (float4*)sT;

        // ---- phase A: async bulk stage of 32 raw rows, both arrays ----
        #pragma unroll 4
        for (int i = lane; i < TILE_V4; i += 32) {
            cp16(dP + i, gp + i);
            cp16(dT + i, gt + i);
        }
        asm volatile("cp.async.commit_group;");
        asm volatile("cp.async.wait_group 0;" ::: "memory");
        __syncwarp();

        // ---- phase B: one lane = one row, sequential conflict-free LDS ----
        process_row(sP + lane * CH, sT + lane * CH, s_a, s_b, l1_acc, vel_acc);

        __syncwarp();   // all lanes done reading before next tile overwrites
    }

    // tail rows (rows % 32), straight from gmem (empty for this dataset)
    if (gwarp == 0) {
        for (int row = tiles * RPT + lane; row < rows; row += 32) {
            process_row(preds + (size_t)row * CH, targets + (size_t)row * CH,
                        s_a, s_b, l1_acc, vel_acc);
        }
    }

    // ---- warp reduce ----
    #pragma unroll
    for (int o = 16; o > 0; o >>= 1) {
        l1_acc  += __shfl_down_sync(0xFFFFFFFFu, l1_acc,  o);
        vel_acc += __shfl_down_sync(0xFFFFFFFFu, vel_acc, o);
    }
    if (lane == 0) { s_red[0][wloc] = l1_acc; s_red[1][wloc] = vel_acc; }
    __syncthreads();

    // ---- block reduce + 2 double atomics per block (296 total) ----
    if (threadIdx.x == 0) {
        float a = 0.f, v = 0.f;
        #pragma unroll
        for (int i = 0; i < NWARP; i++) { a += s_red[0][i]; v += s_red[1][i]; }
        atomicAdd(&g_acc[0], (double)a);
        atomicAdd(&g_acc[1], (double)v);
    }
}

__global__ void finalize_kernel(float* __restrict__ out,
                                double n_l1, double n_vel)
{
    double l1  = g_acc[0] / n_l1;
    double vel = g_acc[1] / n_vel;
    out[0] = (float)(l1 + 0.1 * vel);
}

extern "C" void kernel_launch(void* const* d_in, const int* in_sizes, int n_in,
                              void* d_out, int out_size)
{
    const float* preds   = (const float*)d_in[0];
    const float* targets = (const float*)d_in[1];
    float* out = (float*)d_out;

    int n     = in_sizes[0];
    int rows  = n / CH;            // B*T = 131072
    int tiles = rows / RPT;        // 4096

    cudaFuncSetAttribute(reg_loss_kernel,
                         cudaFuncAttributeMaxDynamicSharedMemorySize, SMEM_BYTES);

    init_acc_kernel<<<1, 1>>>();

    // 148 blocks -> 1 per SM (193KB smem), 740 independent warps
    reg_loss_kernel<<<148, THREADS, SMEM_BYTES>>>(preds, targets, tiles, rows);

    finalize_kernel<<<1, 1>>>(out,
                              (double)rows * (double)CH,
                              (double)rows * (double)(N_EDGES * 3));
}